// round 9
// baseline (speedup 1.0000x reference)
#include <cuda_runtime.h>
#include <math.h>

#define N_SENT      262144
#define N_BAGS      4096
#define HIDDEN      256
#define NUM_CLASSES 53
#define CH          1024   // smem-staged logits capacity (covers max bag ~600)

// Static scratch (no allocs allowed).
__device__ float2       g_logits[N_SENT];
__device__ float        g_repre[N_BAGS * 512];   // [B, 2*HIDDEN]
__device__ unsigned int g_ctr;                   // persistent-K2 work counter

// ---------------------------------------------------------------------------
// K1: per-sentence logits. 4 sentences per warp -> 8 float4 loads in flight.
//     Also zeroes the K2 work counter.
// ---------------------------------------------------------------------------
__global__ __launch_bounds__(256) void logits_kernel(
    const float4* __restrict__ x4,     // [N_SENT, 64]
    const float*  __restrict__ e0,     // [14, 256]
    const float*  __restrict__ e1,     // [53, 256]
    const int*    __restrict__ rl,     // [53, 2]
    const int*    __restrict__ li)     // [N_SENT]
{
    if (blockIdx.x == 0 && threadIdx.x == 0) g_ctr = 0;

    const int warp = threadIdx.x >> 5;
    const int lane = threadIdx.x & 31;
    const int base = (blockIdx.x * 8 + warp) * 4;   // grid 8192 covers N_SENT

    int cs[4];
    #pragma unroll
    for (int s = 0; s < 4; s++) cs[s] = __ldg(li + base + s);

    const float4* xp = x4 + (size_t)base * 64 + lane * 2;
    float4 XA[4], XB[4];
    #pragma unroll
    for (int s = 0; s < 4; s++) {
        XA[s] = __ldg(xp + s * 64);
        XB[s] = __ldg(xp + s * 64 + 1);
    }

    float g0[4], g1[4];
    #pragma unroll
    for (int s = 0; s < 4; s++) {
        int l0 = __ldg(rl + 2 * cs[s]);
        int l1 = __ldg(rl + 2 * cs[s] + 1);
        const float4* p0 = reinterpret_cast<const float4*>(e0 + l0 * HIDDEN) + lane * 2;
        const float4* p1 = reinterpret_cast<const float4*>(e1 + l1 * HIDDEN) + lane * 2;
        float4 ea = __ldg(p0), eb = __ldg(p0 + 1);
        float4 fa = __ldg(p1), fb = __ldg(p1 + 1);
        float4 xa = XA[s], xb = XB[s];
        g0[s] = xa.x*ea.x + xa.y*ea.y + xa.z*ea.z + xa.w*ea.w
              + xb.x*eb.x + xb.y*eb.y + xb.z*eb.z + xb.w*eb.w;
        g1[s] = xa.x*fa.x + xa.y*fa.y + xa.z*fa.z + xa.w*fa.w
              + xb.x*fb.x + xb.y*fb.y + xb.z*fb.z + xb.w*fb.w;
    }

    #pragma unroll
    for (int s = 0; s < 4; s++) {
        #pragma unroll
        for (int o = 16; o; o >>= 1) {
            g0[s] += __shfl_xor_sync(0xffffffffu, g0[s], o);
            g1[s] += __shfl_xor_sync(0xffffffffu, g1[s], o);
        }
    }
    if (lane == 0) {
        #pragma unroll
        for (int s = 0; s < 4; s++)
            g_logits[base + s] = make_float2(g0[s], g1[s]);
    }
}

// ---------------------------------------------------------------------------
// K2: persistent work-stealing bag kernel. Per bag: stage logits in smem,
//     softmax, float4 weighted sum, write repre. NO epilogue GEMM here.
// ---------------------------------------------------------------------------
__global__ __launch_bounds__(256) void bag_kernel(
    const float4* __restrict__ x4,     // [N_SENT, 64]
    const int*    __restrict__ scope)  // [N_BAGS + 1]
{
    __shared__ float2   s_w[CH];
    __shared__ float    s_red[16];
    __shared__ float    s_re[2 * HIDDEN];
    __shared__ unsigned s_bag;

    const int tid  = threadIdx.x;
    const int lane = tid & 31;
    const int warp = tid >> 5;
    const int sg   = tid >> 6;         // sentence subgroup 0..3
    const int d4   = tid & 63;         // float4 column

    for (;;) {
        __syncthreads();               // protect s_bag / smem reuse
        if (tid == 0) s_bag = atomicAdd(&g_ctr, 1u);
        __syncthreads();
        const unsigned b = s_bag;
        if (b >= N_BAGS) break;

        const int s0 = __ldg(scope + b);
        const int s1 = __ldg(scope + b + 1);
        const int n  = s1 - s0;

        float m0, m1, inv0, inv1;
        const bool fast = (n <= CH);

        if (fast) {
            // stage logits once
            for (int i = tid; i < n; i += 256) s_w[i] = g_logits[s0 + i];
            __syncthreads();
            float lm0 = -INFINITY, lm1 = -INFINITY;
            for (int i = tid; i < n; i += 256) {
                float2 v = s_w[i];
                lm0 = fmaxf(lm0, v.x); lm1 = fmaxf(lm1, v.y);
            }
            #pragma unroll
            for (int o = 16; o; o >>= 1) {
                lm0 = fmaxf(lm0, __shfl_xor_sync(0xffffffffu, lm0, o));
                lm1 = fmaxf(lm1, __shfl_xor_sync(0xffffffffu, lm1, o));
            }
            if (lane == 0) { s_red[warp] = lm0; s_red[8 + warp] = lm1; }
            __syncthreads();
            m0 = s_red[0]; m1 = s_red[8];
            #pragma unroll
            for (int k = 1; k < 8; k++) {
                m0 = fmaxf(m0, s_red[k]); m1 = fmaxf(m1, s_red[8 + k]);
            }
            __syncthreads();

            float ls0 = 0.f, ls1 = 0.f;
            for (int i = tid; i < n; i += 256) {
                float2 v = s_w[i];
                ls0 += __expf(v.x - m0); ls1 += __expf(v.y - m1);
            }
            #pragma unroll
            for (int o = 16; o; o >>= 1) {
                ls0 += __shfl_xor_sync(0xffffffffu, ls0, o);
                ls1 += __shfl_xor_sync(0xffffffffu, ls1, o);
            }
            if (lane == 0) { s_red[warp] = ls0; s_red[8 + warp] = ls1; }
            __syncthreads();
            float su0 = 0.f, su1 = 0.f;
            #pragma unroll
            for (int k = 0; k < 8; k++) { su0 += s_red[k]; su1 += s_red[8 + k]; }
            inv0 = 1.0f / su0; inv1 = 1.0f / su1;

            // weights in place
            for (int i = tid; i < n; i += 256) {
                float2 v = s_w[i];
                s_w[i] = make_float2(__expf(v.x - m0) * inv0,
                                     __expf(v.y - m1) * inv1);
            }
        } else {
            // stats from global (rare path)
            float lm0 = -INFINITY, lm1 = -INFINITY;
            for (int i = tid; i < n; i += 256) {
                float2 v = g_logits[s0 + i];
                lm0 = fmaxf(lm0, v.x); lm1 = fmaxf(lm1, v.y);
            }
            #pragma unroll
            for (int o = 16; o; o >>= 1) {
                lm0 = fmaxf(lm0, __shfl_xor_sync(0xffffffffu, lm0, o));
                lm1 = fmaxf(lm1, __shfl_xor_sync(0xffffffffu, lm1, o));
            }
            if (lane == 0) { s_red[warp] = lm0; s_red[8 + warp] = lm1; }
            __syncthreads();
            m0 = s_red[0]; m1 = s_red[8];
            #pragma unroll
            for (int k = 1; k < 8; k++) {
                m0 = fmaxf(m0, s_red[k]); m1 = fmaxf(m1, s_red[8 + k]);
            }
            __syncthreads();
            float ls0 = 0.f, ls1 = 0.f;
            for (int i = tid; i < n; i += 256) {
                float2 v = g_logits[s0 + i];
                ls0 += __expf(v.x - m0); ls1 += __expf(v.y - m1);
            }
            #pragma unroll
            for (int o = 16; o; o >>= 1) {
                ls0 += __shfl_xor_sync(0xffffffffu, ls0, o);
                ls1 += __shfl_xor_sync(0xffffffffu, ls1, o);
            }
            if (lane == 0) { s_red[warp] = ls0; s_red[8 + warp] = ls1; }
            __syncthreads();
            float su0 = 0.f, su1 = 0.f;
            #pragma unroll
            for (int k = 0; k < 8; k++) { su0 += s_red[k]; su1 += s_red[8 + k]; }
            inv0 = 1.0f / su0; inv1 = 1.0f / su1;
        }

        // ---- weighted accumulation ----
        float4 a0 = make_float4(0.f, 0.f, 0.f, 0.f);
        float4 a1 = make_float4(0.f, 0.f, 0.f, 0.f);

        for (int cstart = 0; cstart < n; cstart += CH) {
            int cn = min(CH, n - cstart);
            __syncthreads();
            if (!fast) {   // stage this chunk's weights
                for (int i = tid; i < cn; i += 256) {
                    float2 v = g_logits[s0 + cstart + i];
                    s_w[i] = make_float2(__expf(v.x - m0) * inv0,
                                         __expf(v.y - m1) * inv1);
                }
            }
            __syncthreads();

            const float4* xb = x4 + (size_t)(s0 + cstart) * 64 + d4;
            int j = sg;
            for (; j + 12 < cn; j += 16) {
                float4 x0 = __ldg(xb + (size_t)(j)      * 64);
                float4 x1 = __ldg(xb + (size_t)(j + 4)  * 64);
                float4 x2 = __ldg(xb + (size_t)(j + 8)  * 64);
                float4 x3 = __ldg(xb + (size_t)(j + 12) * 64);
                float2 w0 = s_w[j], w1 = s_w[j + 4], w2 = s_w[j + 8], w3 = s_w[j + 12];
                a0.x += w0.x*x0.x; a0.y += w0.x*x0.y; a0.z += w0.x*x0.z; a0.w += w0.x*x0.w;
                a1.x += w0.y*x0.x; a1.y += w0.y*x0.y; a1.z += w0.y*x0.z; a1.w += w0.y*x0.w;
                a0.x += w1.x*x1.x; a0.y += w1.x*x1.y; a0.z += w1.x*x1.z; a0.w += w1.x*x1.w;
                a1.x += w1.y*x1.x; a1.y += w1.y*x1.y; a1.z += w1.y*x1.z; a1.w += w1.y*x1.w;
                a0.x += w2.x*x2.x; a0.y += w2.x*x2.y; a0.z += w2.x*x2.z; a0.w += w2.x*x2.w;
                a1.x += w2.y*x2.x; a1.y += w2.y*x2.y; a1.z += w2.y*x2.z; a1.w += w2.y*x2.w;
                a0.x += w3.x*x3.x; a0.y += w3.x*x3.y; a0.z += w3.x*x3.z; a0.w += w3.x*x3.w;
                a1.x += w3.y*x3.x; a1.y += w3.y*x3.y; a1.z += w3.y*x3.z; a1.w += w3.y*x3.w;
            }
            for (; j < cn; j += 4) {
                float4 xv = __ldg(xb + (size_t)j * 64);
                float2 w  = s_w[j];
                a0.x += w.x*xv.x; a0.y += w.x*xv.y; a0.z += w.x*xv.z; a0.w += w.x*xv.w;
                a1.x += w.y*xv.x; a1.y += w.y*xv.y; a1.z += w.y*xv.z; a1.w += w.y*xv.w;
            }
        }

        // ---- combine 4 subgroups ----
        __syncthreads();
        s_re[tid]       = 0.f;
        s_re[256 + tid] = 0.f;
        __syncthreads();
        #pragma unroll
        for (int g = 0; g < 4; g++) {
            if (sg == g) {
                int base = d4 * 4;
                s_re[base + 0] += a0.x; s_re[base + 1] += a0.y;
                s_re[base + 2] += a0.z; s_re[base + 3] += a0.w;
                s_re[256 + base + 0] += a1.x; s_re[256 + base + 1] += a1.y;
                s_re[256 + base + 2] += a1.z; s_re[256 + base + 3] += a1.w;
            }
            __syncthreads();
        }

        // ---- write repre (coalesced float4) ----
        if (tid < 128)
            reinterpret_cast<float4*>(g_repre)[b * 128 + tid] =
                reinterpret_cast<float4*>(s_re)[tid];
    }
}

// ---------------------------------------------------------------------------
// K3: out[4096,53] = repre[4096,512] @ disc[53,512]^T + bias.
//     128 blocks x 32 bags; k chunked by 64; pad-68 smem rows (conflict-free);
//     per-thread tile: 4 bags x 2 classes, float4 over k.
// ---------------------------------------------------------------------------
#define K3_BAGS 32
#define KC      64
__global__ __launch_bounds__(256) void gemm_kernel(
    const float* __restrict__ disc,    // [53, 512]
    const float* __restrict__ bias,    // [53]
    float*       __restrict__ out)     // [N_BAGS, 53]
{
    __shared__ float s_rep[K3_BAGS * 68];   // [32][68]
    __shared__ float s_disc[NUM_CLASSES * 68];

    const int tid  = threadIdx.x;
    const int lane = tid & 31;
    const int warp = tid >> 5;
    const int bag0 = blockIdx.x * K3_BAGS;

    float acc00 = 0.f, acc01 = 0.f, acc10 = 0.f, acc11 = 0.f,
          acc20 = 0.f, acc21 = 0.f, acc30 = 0.f, acc31 = 0.f;

    const float4* rep4 = reinterpret_cast<const float4*>(g_repre);

    for (int k0 = 0; k0 < 512; k0 += KC) {
        __syncthreads();
        // stage rep tile: 32 bags x 64 k = 512 float4
        #pragma unroll
        for (int p = 0; p < 2; p++) {
            int f = tid + p * 256;                 // 0..511
            int bg = f >> 4, q = f & 15;
            float4 v = rep4[(size_t)(bag0 + bg) * 128 + (k0 >> 2) + q];
            *reinterpret_cast<float4*>(&s_rep[bg * 68 + q * 4]) = v;
        }
        // stage disc tile: 53 rows x 64 k = 848 float4
        #pragma unroll
        for (int p = 0; p < 4; p++) {
            int f = tid + p * 256;
            if (f < NUM_CLASSES * 16) {
                int c = f >> 4, q = f & 15;
                float4 v = __ldg(reinterpret_cast<const float4*>(disc + c * 512 + k0) + q);
                *reinterpret_cast<float4*>(&s_disc[c * 68 + q * 4]) = v;
            }
        }
        __syncthreads();

        const int c1 = 32 + lane;          // second class (valid if < 53)
        const int c1c = (c1 < NUM_CLASSES) ? c1 : lane;   // clamp; result discarded
        #pragma unroll
        for (int q = 0; q < 16; q++) {
            float4 bv0 = *reinterpret_cast<const float4*>(&s_disc[lane * 68 + q * 4]);
            float4 bv1 = *reinterpret_cast<const float4*>(&s_disc[c1c * 68 + q * 4]);
            float4 a0v = *reinterpret_cast<const float4*>(&s_rep[(warp * 4 + 0) * 68 + q * 4]);
            float4 a1v = *reinterpret_cast<const float4*>(&s_rep[(warp * 4 + 1) * 68 + q * 4]);
            float4 a2v = *reinterpret_cast<const float4*>(&s_rep[(warp * 4 + 2) * 68 + q * 4]);
            float4 a3v = *reinterpret_cast<const float4*>(&s_rep[(warp * 4 + 3) * 68 + q * 4]);
            acc00 += a0v.x*bv0.x + a0v.y*bv0.y + a0v.z*bv0.z + a0v.w*bv0.w;
            acc01 += a0v.x*bv1.x + a0v.y*bv1.y + a0v.z*bv1.z + a0v.w*bv1.w;
            acc10 += a1v.x*bv0.x + a1v.y*bv0.y + a1v.z*bv0.z + a1v.w*bv0.w;
            acc11 += a1v.x*bv1.x + a1v.y*bv1.y + a1v.z*bv1.z + a1v.w*bv1.w;
            acc20 += a2v.x*bv0.x + a2v.y*bv0.y + a2v.z*bv0.z + a2v.w*bv0.w;
            acc21 += a2v.x*bv1.x + a2v.y*bv1.y + a2v.z*bv1.z + a2v.w*bv1.w;
            acc30 += a3v.x*bv0.x + a3v.y*bv0.y + a3v.z*bv0.z + a3v.w*bv0.w;
            acc31 += a3v.x*bv1.x + a3v.y*bv1.y + a3v.z*bv1.z + a3v.w*bv1.w;
        }
    }

    const float b0v = __ldg(bias + lane);
    const int   c1  = 32 + lane;
    const float b1v = (c1 < NUM_CLASSES) ? __ldg(bias + c1) : 0.f;
    const int   bb  = bag0 + warp * 4;

    out[(bb + 0) * NUM_CLASSES + lane] = acc00 + b0v;
    out[(bb + 1) * NUM_CLASSES + lane] = acc10 + b0v;
    out[(bb + 2) * NUM_CLASSES + lane] = acc20 + b0v;
    out[(bb + 3) * NUM_CLASSES + lane] = acc30 + b0v;
    if (c1 < NUM_CLASSES) {
        out[(bb + 0) * NUM_CLASSES + c1] = acc01 + b1v;
        out[(bb + 1) * NUM_CLASSES + c1] = acc11 + b1v;
        out[(bb + 2) * NUM_CLASSES + c1] = acc21 + b1v;
        out[(bb + 3) * NUM_CLASSES + c1] = acc31 + b1v;
    }
}

// ---------------------------------------------------------------------------
extern "C" void kernel_launch(void* const* d_in, const int* in_sizes, int n_in,
                              void* d_out, int out_size)
{
    const float* x    = (const float*)d_in[0];   // [262144, 256]
    const float* e0   = (const float*)d_in[1];   // [14, 256]
    const float* e1   = (const float*)d_in[2];   // [53, 256]
    const float* disc = (const float*)d_in[3];   // [53, 512]
    const float* bias = (const float*)d_in[4];   // [53]
    const int*   rl   = (const int*)d_in[5];     // [53, 2]
    const int*   li   = (const int*)d_in[6];     // [262144]
    const int*   sc   = (const int*)d_in[7];     // [4097]
    float* out = (float*)d_out;                  // [4096, 53]

    logits_kernel<<<N_SENT / 32, 256>>>((const float4*)x, e0, e1, rl, li);
    bag_kernel<<<152 * 7, 256>>>((const float4*)x, sc);
    gemm_kernel<<<N_BAGS / K3_BAGS, 256>>>(disc, bias, out);
}

// round 10
// speedup vs baseline: 1.0313x; 1.0313x over previous
#include <cuda_runtime.h>
#include <math.h>

#define N_SENT      262144
#define N_BAGS      4096
#define HIDDEN      256
#define NUM_CLASSES 53
#define CH          512    // weight chunk staged in smem per iteration

// Static scratch (no allocs allowed).
__device__ float2 g_logits[N_SENT];
__device__ float  g_repre[N_BAGS * 512];   // [B, 2*HIDDEN]

// ---------------------------------------------------------------------------
// K1: per-sentence logits. 4 sentences per warp.
//     FIXED addressing: each row read as two contiguous 512B halves
//     ([lane] and [lane+32]) -> 4 wavefronts per LDG.128, not 8.
// ---------------------------------------------------------------------------
__global__ __launch_bounds__(256) void logits_kernel(
    const float4* __restrict__ x4,     // [N_SENT, 64]
    const float*  __restrict__ e0,     // [14, 256]
    const float*  __restrict__ e1,     // [53, 256]
    const int*    __restrict__ rl,     // [53, 2]
    const int*    __restrict__ li)     // [N_SENT]
{
    const int warp = threadIdx.x >> 5;
    const int lane = threadIdx.x & 31;
    const int base = (blockIdx.x * 8 + warp) * 4;   // grid 8192 covers N_SENT

    int cs[4];
    #pragma unroll
    for (int s = 0; s < 4; s++) cs[s] = __ldg(li + base + s);

    // 8 independent x loads: contiguous halves of each 1KB row.
    const float4* xp = x4 + (size_t)base * 64;
    float4 XA[4], XB[4];
    #pragma unroll
    for (int s = 0; s < 4; s++) {
        XA[s] = __ldg(xp + s * 64 + lane);        // dims [4*lane .. 4*lane+3]
        XB[s] = __ldg(xp + s * 64 + 32 + lane);   // dims [128+4*lane ..]
    }

    float g0[4], g1[4];
    #pragma unroll
    for (int s = 0; s < 4; s++) {
        int l0 = __ldg(rl + 2 * cs[s]);
        int l1 = __ldg(rl + 2 * cs[s] + 1);
        const float4* p0 = reinterpret_cast<const float4*>(e0 + l0 * HIDDEN);
        const float4* p1 = reinterpret_cast<const float4*>(e1 + l1 * HIDDEN);
        float4 ea = __ldg(p0 + lane), eb = __ldg(p0 + 32 + lane);
        float4 fa = __ldg(p1 + lane), fb = __ldg(p1 + 32 + lane);
        float4 xa = XA[s], xb = XB[s];
        g0[s] = xa.x*ea.x + xa.y*ea.y + xa.z*ea.z + xa.w*ea.w
              + xb.x*eb.x + xb.y*eb.y + xb.z*eb.z + xb.w*eb.w;
        g1[s] = xa.x*fa.x + xa.y*fa.y + xa.z*fa.z + xa.w*fa.w
              + xb.x*fb.x + xb.y*fb.y + xb.z*fb.z + xb.w*fb.w;
    }

    #pragma unroll
    for (int s = 0; s < 4; s++) {
        #pragma unroll
        for (int o = 16; o; o >>= 1) {
            g0[s] += __shfl_xor_sync(0xffffffffu, g0[s], o);
            g1[s] += __shfl_xor_sync(0xffffffffu, g1[s], o);
        }
    }
    if (lane == 0) {
        #pragma unroll
        for (int s = 0; s < 4; s++)
            g_logits[base + s] = make_float2(g0[s], g1[s]);
    }
}

// ---------------------------------------------------------------------------
// K2: one block per bag (plain grid). Softmax stats from g_logits (L2-hot),
//     chunk-staged weights in smem, float4 weighted sum, write repre.
//     NO epilogue GEMM here.
// ---------------------------------------------------------------------------
__global__ __launch_bounds__(256) void bag_kernel(
    const float4* __restrict__ x4,     // [N_SENT, 64]
    const int*    __restrict__ scope)  // [N_BAGS + 1]
{
    __shared__ float2 s_w[CH];
    __shared__ float  s_red[16];
    __shared__ float  s_re[2 * HIDDEN];

    const int b    = blockIdx.x;
    const int tid  = threadIdx.x;
    const int lane = tid & 31;
    const int warp = tid >> 5;
    const int sg   = tid >> 6;         // sentence subgroup 0..3
    const int d4   = tid & 63;         // float4 column

    const int s0 = __ldg(scope + b);
    const int s1 = __ldg(scope + b + 1);
    const int n  = s1 - s0;

    // ---- softmax stats ----
    float lm0 = -INFINITY, lm1 = -INFINITY;
    for (int i = tid; i < n; i += 256) {
        float2 v = g_logits[s0 + i];
        lm0 = fmaxf(lm0, v.x); lm1 = fmaxf(lm1, v.y);
    }
    #pragma unroll
    for (int o = 16; o; o >>= 1) {
        lm0 = fmaxf(lm0, __shfl_xor_sync(0xffffffffu, lm0, o));
        lm1 = fmaxf(lm1, __shfl_xor_sync(0xffffffffu, lm1, o));
    }
    if (lane == 0) { s_red[warp] = lm0; s_red[8 + warp] = lm1; }
    __syncthreads();
    float m0 = s_red[0], m1 = s_red[8];
    #pragma unroll
    for (int k = 1; k < 8; k++) {
        m0 = fmaxf(m0, s_red[k]); m1 = fmaxf(m1, s_red[8 + k]);
    }
    __syncthreads();

    float ls0 = 0.f, ls1 = 0.f;
    for (int i = tid; i < n; i += 256) {
        float2 v = g_logits[s0 + i];
        ls0 += __expf(v.x - m0); ls1 += __expf(v.y - m1);
    }
    #pragma unroll
    for (int o = 16; o; o >>= 1) {
        ls0 += __shfl_xor_sync(0xffffffffu, ls0, o);
        ls1 += __shfl_xor_sync(0xffffffffu, ls1, o);
    }
    if (lane == 0) { s_red[warp] = ls0; s_red[8 + warp] = ls1; }
    __syncthreads();
    float su0 = 0.f, su1 = 0.f;
    #pragma unroll
    for (int k = 0; k < 8; k++) { su0 += s_red[k]; su1 += s_red[8 + k]; }
    const float inv0 = 1.0f / su0;   // empty bag: loop below no-op
    const float inv1 = 1.0f / su1;

    // ---- weighted accumulation ----
    float4 a0 = make_float4(0.f, 0.f, 0.f, 0.f);
    float4 a1 = make_float4(0.f, 0.f, 0.f, 0.f);

    for (int cstart = 0; cstart < n; cstart += CH) {
        int cn = min(CH, n - cstart);
        __syncthreads();
        for (int i = tid; i < cn; i += 256) {
            float2 v = g_logits[s0 + cstart + i];
            s_w[i] = make_float2(__expf(v.x - m0) * inv0,
                                 __expf(v.y - m1) * inv1);
        }
        __syncthreads();

        const float4* xb = x4 + (size_t)(s0 + cstart) * 64 + d4;
        int j = sg;
        for (; j + 12 < cn; j += 16) {
            float4 x0 = __ldg(xb + (size_t)(j)      * 64);
            float4 x1 = __ldg(xb + (size_t)(j + 4)  * 64);
            float4 x2 = __ldg(xb + (size_t)(j + 8)  * 64);
            float4 x3 = __ldg(xb + (size_t)(j + 12) * 64);
            float2 w0 = s_w[j], w1 = s_w[j + 4], w2 = s_w[j + 8], w3 = s_w[j + 12];
            a0.x += w0.x*x0.x; a0.y += w0.x*x0.y; a0.z += w0.x*x0.z; a0.w += w0.x*x0.w;
            a1.x += w0.y*x0.x; a1.y += w0.y*x0.y; a1.z += w0.y*x0.z; a1.w += w0.y*x0.w;
            a0.x += w1.x*x1.x; a0.y += w1.x*x1.y; a0.z += w1.x*x1.z; a0.w += w1.x*x1.w;
            a1.x += w1.y*x1.x; a1.y += w1.y*x1.y; a1.z += w1.y*x1.z; a1.w += w1.y*x1.w;
            a0.x += w2.x*x2.x; a0.y += w2.x*x2.y; a0.z += w2.x*x2.z; a0.w += w2.x*x2.w;
            a1.x += w2.y*x2.x; a1.y += w2.y*x2.y; a1.z += w2.y*x2.z; a1.w += w2.y*x2.w;
            a0.x += w3.x*x3.x; a0.y += w3.x*x3.y; a0.z += w3.x*x3.z; a0.w += w3.x*x3.w;
            a1.x += w3.y*x3.x; a1.y += w3.y*x3.y; a1.z += w3.y*x3.z; a1.w += w3.y*x3.w;
        }
        for (; j < cn; j += 4) {
            float4 xv = __ldg(xb + (size_t)j * 64);
            float2 w  = s_w[j];
            a0.x += w.x*xv.x; a0.y += w.x*xv.y; a0.z += w.x*xv.z; a0.w += w.x*xv.w;
            a1.x += w.y*xv.x; a1.y += w.y*xv.y; a1.z += w.y*xv.z; a1.w += w.y*xv.w;
        }
    }

    // ---- combine 4 subgroups ----
    __syncthreads();
    s_re[tid]       = 0.f;
    s_re[256 + tid] = 0.f;
    __syncthreads();
    #pragma unroll
    for (int g = 0; g < 4; g++) {
        if (sg == g) {
            int bb = d4 * 4;
            s_re[bb + 0] += a0.x; s_re[bb + 1] += a0.y;
            s_re[bb + 2] += a0.z; s_re[bb + 3] += a0.w;
            s_re[256 + bb + 0] += a1.x; s_re[256 + bb + 1] += a1.y;
            s_re[256 + bb + 2] += a1.z; s_re[256 + bb + 3] += a1.w;
        }
        __syncthreads();
    }

    // ---- write repre (coalesced float4) ----
    if (tid < 128)
        reinterpret_cast<float4*>(g_repre)[b * 128 + tid] =
            reinterpret_cast<float4*>(s_re)[tid];
}

// ---------------------------------------------------------------------------
// K3: out[4096,53] = repre[4096,512] @ disc[53,512]^T + bias.
//     128 blocks x 32 bags; k chunked by 64; pad-68 smem rows;
//     per-thread tile: 4 bags x 2 classes, float4 over k.
// ---------------------------------------------------------------------------
#define K3_BAGS 32
#define KC      64
__global__ __launch_bounds__(256) void gemm_kernel(
    const float* __restrict__ disc,    // [53, 512]
    const float* __restrict__ bias,    // [53]
    float*       __restrict__ out)     // [N_BAGS, 53]
{
    __shared__ float s_rep[K3_BAGS * 68];
    __shared__ float s_disc[NUM_CLASSES * 68];

    const int tid  = threadIdx.x;
    const int lane = tid & 31;
    const int warp = tid >> 5;
    const int bag0 = blockIdx.x * K3_BAGS;

    float acc00 = 0.f, acc01 = 0.f, acc10 = 0.f, acc11 = 0.f,
          acc20 = 0.f, acc21 = 0.f, acc30 = 0.f, acc31 = 0.f;

    const float4* rep4 = reinterpret_cast<const float4*>(g_repre);

    for (int k0 = 0; k0 < 512; k0 += KC) {
        __syncthreads();
        #pragma unroll
        for (int p = 0; p < 2; p++) {
            int f = tid + p * 256;
            int bg = f >> 4, q = f & 15;
            float4 v = rep4[(size_t)(bag0 + bg) * 128 + (k0 >> 2) + q];
            *reinterpret_cast<float4*>(&s_rep[bg * 68 + q * 4]) = v;
        }
        #pragma unroll
        for (int p = 0; p < 4; p++) {
            int f = tid + p * 256;
            if (f < NUM_CLASSES * 16) {
                int c = f >> 4, q = f & 15;
                float4 v = __ldg(reinterpret_cast<const float4*>(disc + c * 512 + k0) + q);
                *reinterpret_cast<float4*>(&s_disc[c * 68 + q * 4]) = v;
            }
        }
        __syncthreads();

        const int c1  = 32 + lane;
        const int c1c = (c1 < NUM_CLASSES) ? c1 : lane;
        #pragma unroll
        for (int q = 0; q < 16; q++) {
            float4 bv0 = *reinterpret_cast<const float4*>(&s_disc[lane * 68 + q * 4]);
            float4 bv1 = *reinterpret_cast<const float4*>(&s_disc[c1c * 68 + q * 4]);
            float4 a0v = *reinterpret_cast<const float4*>(&s_rep[(warp * 4 + 0) * 68 + q * 4]);
            float4 a1v = *reinterpret_cast<const float4*>(&s_rep[(warp * 4 + 1) * 68 + q * 4]);
            float4 a2v = *reinterpret_cast<const float4*>(&s_rep[(warp * 4 + 2) * 68 + q * 4]);
            float4 a3v = *reinterpret_cast<const float4*>(&s_rep[(warp * 4 + 3) * 68 + q * 4]);
            acc00 += a0v.x*bv0.x + a0v.y*bv0.y + a0v.z*bv0.z + a0v.w*bv0.w;
            acc01 += a0v.x*bv1.x + a0v.y*bv1.y + a0v.z*bv1.z + a0v.w*bv1.w;
            acc10 += a1v.x*bv0.x + a1v.y*bv0.y + a1v.z*bv0.z + a1v.w*bv0.w;
            acc11 += a1v.x*bv1.x + a1v.y*bv1.y + a1v.z*bv1.z + a1v.w*bv1.w;
            acc20 += a2v.x*bv0.x + a2v.y*bv0.y + a2v.z*bv0.z + a2v.w*bv0.w;
            acc21 += a2v.x*bv1.x + a2v.y*bv1.y + a2v.z*bv1.z + a2v.w*bv1.w;
            acc30 += a3v.x*bv0.x + a3v.y*bv0.y + a3v.z*bv0.z + a3v.w*bv0.w;
            acc31 += a3v.x*bv1.x + a3v.y*bv1.y + a3v.z*bv1.z + a3v.w*bv1.w;
        }
    }

    const float b0v = __ldg(bias + lane);
    const int   c1  = 32 + lane;
    const float b1v = (c1 < NUM_CLASSES) ? __ldg(bias + c1) : 0.f;
    const int   bb  = bag0 + warp * 4;

    out[(bb + 0) * NUM_CLASSES + lane] = acc00 + b0v;
    out[(bb + 1) * NUM_CLASSES + lane] = acc10 + b0v;
    out[(bb + 2) * NUM_CLASSES + lane] = acc20 + b0v;
    out[(bb + 3) * NUM_CLASSES + lane] = acc30 + b0v;
    if (c1 < NUM_CLASSES) {
        out[(bb + 0) * NUM_CLASSES + c1] = acc01 + b1v;
        out[(bb + 1) * NUM_CLASSES + c1] = acc11 + b1v;
        out[(bb + 2) * NUM_CLASSES + c1] = acc21 + b1v;
        out[(bb + 3) * NUM_CLASSES + c1] = acc31 + b1v;
    }
}

// ---------------------------------------------------------------------------
extern "C" void kernel_launch(void* const* d_in, const int* in_sizes, int n_in,
                              void* d_out, int out_size)
{
    const float* x    = (const float*)d_in[0];   // [262144, 256]
    const float* e0   = (const float*)d_in[1];   // [14, 256]
    const float* e1   = (const float*)d_in[2];   // [53, 256]
    const float* disc = (const float*)d_in[3];   // [53, 512]
    const float* bias = (const float*)d_in[4];   // [53]
    const int*   rl   = (const int*)d_in[5];     // [53, 2]
    const int*   li   = (const int*)d_in[6];     // [262144]
    const int*   sc   = (const int*)d_in[7];     // [4097]
    float* out = (float*)d_out;                  // [4096, 53]

    logits_kernel<<<N_SENT / 32, 256>>>((const float4*)x, e0, e1, rl, li);
    bag_kernel<<<N_BAGS, 256>>>((const float4*)x, sc);
    gemm_kernel<<<N_BAGS / K3_BAGS, 256>>>(disc, bias, out);
}

// round 11
// speedup vs baseline: 1.0754x; 1.0428x over previous
#include <cuda_runtime.h>
#include <math.h>

#define N_SENT      262144
#define N_BAGS      4096
#define HIDDEN      256
#define NUM_CLASSES 53
#define CH          512    // weight chunk staged in smem per iteration

// Static scratch (no allocs allowed).
__device__ float2 g_logits[N_SENT];        // logits, then unnormalized e
__device__ float2 g_stats[N_BAGS];         // (1/sum0, 1/sum1), 0 if empty
__device__ float  g_repre[N_BAGS * 512];   // [B, 2*HIDDEN]

// ---------------------------------------------------------------------------
// K1: per-sentence logits. 4 sentences per warp; contiguous-half addressing.
// ---------------------------------------------------------------------------
__global__ __launch_bounds__(256) void logits_kernel(
    const float4* __restrict__ x4,     // [N_SENT, 64]
    const float*  __restrict__ e0,     // [14, 256]
    const float*  __restrict__ e1,     // [53, 256]
    const int*    __restrict__ rl,     // [53, 2]
    const int*    __restrict__ li)     // [N_SENT]
{
    const int warp = threadIdx.x >> 5;
    const int lane = threadIdx.x & 31;
    const int base = (blockIdx.x * 8 + warp) * 4;   // grid 8192 covers N_SENT

    const int4 liv = __ldg(reinterpret_cast<const int4*>(li + base));
    int cs[4] = {liv.x, liv.y, liv.z, liv.w};

    // 8 independent x loads: contiguous halves of each 1KB row.
    const float4* xp = x4 + (size_t)base * 64;
    float4 XA[4], XB[4];
    #pragma unroll
    for (int s = 0; s < 4; s++) {
        XA[s] = __ldg(xp + s * 64 + lane);
        XB[s] = __ldg(xp + s * 64 + 32 + lane);
    }

    float g0[4], g1[4];
    #pragma unroll
    for (int s = 0; s < 4; s++) {
        int l0 = __ldg(rl + 2 * cs[s]);
        int l1 = __ldg(rl + 2 * cs[s] + 1);
        const float4* p0 = reinterpret_cast<const float4*>(e0 + l0 * HIDDEN);
        const float4* p1 = reinterpret_cast<const float4*>(e1 + l1 * HIDDEN);
        float4 ea = __ldg(p0 + lane), eb = __ldg(p0 + 32 + lane);
        float4 fa = __ldg(p1 + lane), fb = __ldg(p1 + 32 + lane);
        float4 xa = XA[s], xb = XB[s];
        g0[s] = xa.x*ea.x + xa.y*ea.y + xa.z*ea.z + xa.w*ea.w
              + xb.x*eb.x + xb.y*eb.y + xb.z*eb.z + xb.w*eb.w;
        g1[s] = xa.x*fa.x + xa.y*fa.y + xa.z*fa.z + xa.w*fa.w
              + xb.x*fb.x + xb.y*fb.y + xb.z*fb.z + xb.w*fb.w;
    }

    #pragma unroll
    for (int s = 0; s < 4; s++) {
        #pragma unroll
        for (int o = 16; o; o >>= 1) {
            g0[s] += __shfl_xor_sync(0xffffffffu, g0[s], o);
            g1[s] += __shfl_xor_sync(0xffffffffu, g1[s], o);
        }
    }
    if (lane == 0) {
        #pragma unroll
        for (int s = 0; s < 4; s++)
            g_logits[base + s] = make_float2(g0[s], g1[s]);
    }
}

// ---------------------------------------------------------------------------
// K2a: warp-per-bag softmax. Rewrites g_logits with unnormalized e,
//      stores 1/sum (0 for empty bag) in g_stats. All 4096 warps co-resident.
// ---------------------------------------------------------------------------
__global__ __launch_bounds__(256) void weights_kernel(
    const int* __restrict__ scope)     // [N_BAGS + 1]
{
    const int warp = threadIdx.x >> 5;
    const int lane = threadIdx.x & 31;
    const int bag  = blockIdx.x * 8 + warp;   // grid 512 covers N_BAGS

    const int s0 = __ldg(scope + bag);
    const int s1 = __ldg(scope + bag + 1);

    float m0 = -INFINITY, m1 = -INFINITY;
    for (int i = s0 + lane; i < s1; i += 32) {
        float2 v = g_logits[i];
        m0 = fmaxf(m0, v.x); m1 = fmaxf(m1, v.y);
    }
    #pragma unroll
    for (int o = 16; o; o >>= 1) {
        m0 = fmaxf(m0, __shfl_xor_sync(0xffffffffu, m0, o));
        m1 = fmaxf(m1, __shfl_xor_sync(0xffffffffu, m1, o));
    }

    float s0v = 0.f, s1v = 0.f;
    for (int i = s0 + lane; i < s1; i += 32) {
        float2 v = g_logits[i];
        float e0v = __expf(v.x - m0);
        float e1v = __expf(v.y - m1);
        s0v += e0v; s1v += e1v;
        g_logits[i] = make_float2(e0v, e1v);
    }
    #pragma unroll
    for (int o = 16; o; o >>= 1) {
        s0v += __shfl_xor_sync(0xffffffffu, s0v, o);
        s1v += __shfl_xor_sync(0xffffffffu, s1v, o);
    }
    if (lane == 0)
        g_stats[bag] = make_float2(s0v > 0.f ? 1.0f / s0v : 0.f,
                                   s1v > 0.f ? 1.0f / s1v : 0.f);
}

// ---------------------------------------------------------------------------
// K2: one block per bag. Pure streaming: copy weight chunk to smem, float4
//     weighted sum (4 subgroups x 64 float4 cols), scale by inv at the end,
//     single-barrier transpose-combine, write repre.
// ---------------------------------------------------------------------------
__global__ __launch_bounds__(256) void bag_kernel(
    const float4* __restrict__ x4,     // [N_SENT, 64]
    const int*    __restrict__ scope)  // [N_BAGS + 1]
{
    __shared__ float2 s_w[CH];         // 4 KB
    __shared__ float  s_c[4 * 512];    // 8 KB combine scratch

    const int b   = blockIdx.x;
    const int tid = threadIdx.x;
    const int sg  = tid >> 6;          // sentence subgroup 0..3
    const int d4  = tid & 63;          // float4 column

    const int s0 = __ldg(scope + b);
    const int s1 = __ldg(scope + b + 1);
    const int n  = s1 - s0;
    const float2 iv = g_stats[b];

    float4 a0 = make_float4(0.f, 0.f, 0.f, 0.f);
    float4 a1 = make_float4(0.f, 0.f, 0.f, 0.f);

    for (int cstart = 0; cstart < n; cstart += CH) {
        int cn = min(CH, n - cstart);
        __syncthreads();
        for (int i = tid; i < cn; i += 256)
            s_w[i] = g_logits[s0 + cstart + i];
        __syncthreads();

        const float4* xb = x4 + (size_t)(s0 + cstart) * 64 + d4;
        int j = sg;
        for (; j + 12 < cn; j += 16) {
            float4 x0 = __ldg(xb + (size_t)(j)      * 64);
            float4 x1 = __ldg(xb + (size_t)(j + 4)  * 64);
            float4 x2 = __ldg(xb + (size_t)(j + 8)  * 64);
            float4 x3 = __ldg(xb + (size_t)(j + 12) * 64);
            float2 w0 = s_w[j], w1 = s_w[j + 4], w2 = s_w[j + 8], w3 = s_w[j + 12];
            a0.x += w0.x*x0.x; a0.y += w0.x*x0.y; a0.z += w0.x*x0.z; a0.w += w0.x*x0.w;
            a1.x += w0.y*x0.x; a1.y += w0.y*x0.y; a1.z += w0.y*x0.z; a1.w += w0.y*x0.w;
            a0.x += w1.x*x1.x; a0.y += w1.x*x1.y; a0.z += w1.x*x1.z; a0.w += w1.x*x1.w;
            a1.x += w1.y*x1.x; a1.y += w1.y*x1.y; a1.z += w1.y*x1.z; a1.w += w1.y*x1.w;
            a0.x += w2.x*x2.x; a0.y += w2.x*x2.y; a0.z += w2.x*x2.z; a0.w += w2.x*x2.w;
            a1.x += w2.y*x2.x; a1.y += w2.y*x2.y; a1.z += w2.y*x2.z; a1.w += w2.y*x2.w;
            a0.x += w3.x*x3.x; a0.y += w3.x*x3.y; a0.z += w3.x*x3.z; a0.w += w3.x*x3.w;
            a1.x += w3.y*x3.x; a1.y += w3.y*x3.y; a1.z += w3.y*x3.z; a1.w += w3.y*x3.w;
        }
        for (; j < cn; j += 4) {
            float4 xv = __ldg(xb + (size_t)j * 64);
            float2 w  = s_w[j];
            a0.x += w.x*xv.x; a0.y += w.x*xv.y; a0.z += w.x*xv.z; a0.w += w.x*xv.w;
            a1.x += w.y*xv.x; a1.y += w.y*xv.y; a1.z += w.y*xv.z; a1.w += w.y*xv.w;
        }
    }

    // scale by 1/sum (0 for empty bag -> repre 0)
    a0.x *= iv.x; a0.y *= iv.x; a0.z *= iv.x; a0.w *= iv.x;
    a1.x *= iv.y; a1.y *= iv.y; a1.z *= iv.y; a1.w *= iv.y;

    // single-barrier combine: s_c[sg][k], k = level*256 + dim
    __syncthreads();   // all readers of s_w done (also orders s_c reuse)
    *reinterpret_cast<float4*>(&s_c[sg * 512 + d4 * 4])       = a0;
    *reinterpret_cast<float4*>(&s_c[sg * 512 + 256 + d4 * 4]) = a1;
    __syncthreads();

    float r0 = s_c[tid]       + s_c[512 + tid]       + s_c[1024 + tid]       + s_c[1536 + tid];
    float r1 = s_c[256 + tid] + s_c[512 + 256 + tid] + s_c[1024 + 256 + tid] + s_c[1536 + 256 + tid];
    g_repre[(size_t)b * 512 + tid]       = r0;
    g_repre[(size_t)b * 512 + 256 + tid] = r1;
}

// ---------------------------------------------------------------------------
// K3: out[4096,53] = repre[4096,512] @ disc[53,512]^T + bias.
// ---------------------------------------------------------------------------
#define K3_BAGS 32
#define KC      64
__global__ __launch_bounds__(256) void gemm_kernel(
    const float* __restrict__ disc,    // [53, 512]
    const float* __restrict__ bias,    // [53]
    float*       __restrict__ out)     // [N_BAGS, 53]
{
    __shared__ float s_rep[K3_BAGS * 68];
    __shared__ float s_disc[NUM_CLASSES * 68];

    const int tid  = threadIdx.x;
    const int lane = tid & 31;
    const int warp = tid >> 5;
    const int bag0 = blockIdx.x * K3_BAGS;

    float acc00 = 0.f, acc01 = 0.f, acc10 = 0.f, acc11 = 0.f,
          acc20 = 0.f, acc21 = 0.f, acc30 = 0.f, acc31 = 0.f;

    const float4* rep4 = reinterpret_cast<const float4*>(g_repre);

    for (int k0 = 0; k0 < 512; k0 += KC) {
        __syncthreads();
        #pragma unroll
        for (int p = 0; p < 2; p++) {
            int f = tid + p * 256;
            int bg = f >> 4, q = f & 15;
            float4 v = rep4[(size_t)(bag0 + bg) * 128 + (k0 >> 2) + q];
            *reinterpret_cast<float4*>(&s_rep[bg * 68 + q * 4]) = v;
        }
        #pragma unroll
        for (int p = 0; p < 4; p++) {
            int f = tid + p * 256;
            if (f < NUM_CLASSES * 16) {
                int c = f >> 4, q = f & 15;
                float4 v = __ldg(reinterpret_cast<const float4*>(disc + c * 512 + k0) + q);
                *reinterpret_cast<float4*>(&s_disc[c * 68 + q * 4]) = v;
            }
        }
        __syncthreads();

        const int c1  = 32 + lane;
        const int c1c = (c1 < NUM_CLASSES) ? c1 : lane;
        #pragma unroll
        for (int q = 0; q < 16; q++) {
            float4 bv0 = *reinterpret_cast<const float4*>(&s_disc[lane * 68 + q * 4]);
            float4 bv1 = *reinterpret_cast<const float4*>(&s_disc[c1c * 68 + q * 4]);
            float4 a0v = *reinterpret_cast<const float4*>(&s_rep[(warp * 4 + 0) * 68 + q * 4]);
            float4 a1v = *reinterpret_cast<const float4*>(&s_rep[(warp * 4 + 1) * 68 + q * 4]);
            float4 a2v = *reinterpret_cast<const float4*>(&s_rep[(warp * 4 + 2) * 68 + q * 4]);
            float4 a3v = *reinterpret_cast<const float4*>(&s_rep[(warp * 4 + 3) * 68 + q * 4]);
            acc00 += a0v.x*bv0.x + a0v.y*bv0.y + a0v.z*bv0.z + a0v.w*bv0.w;
            acc01 += a0v.x*bv1.x + a0v.y*bv1.y + a0v.z*bv1.z + a0v.w*bv1.w;
            acc10 += a1v.x*bv0.x + a1v.y*bv0.y + a1v.z*bv0.z + a1v.w*bv0.w;
            acc11 += a1v.x*bv1.x + a1v.y*bv1.y + a1v.z*bv1.z + a1v.w*bv1.w;
            acc20 += a2v.x*bv0.x + a2v.y*bv0.y + a2v.z*bv0.z + a2v.w*bv0.w;
            acc21 += a2v.x*bv1.x + a2v.y*bv1.y + a2v.z*bv1.z + a2v.w*bv1.w;
            acc30 += a3v.x*bv0.x + a3v.y*bv0.y + a3v.z*bv0.z + a3v.w*bv0.w;
            acc31 += a3v.x*bv1.x + a3v.y*bv1.y + a3v.z*bv1.z + a3v.w*bv1.w;
        }
    }

    const float b0v = __ldg(bias + lane);
    const int   c1  = 32 + lane;
    const float b1v = (c1 < NUM_CLASSES) ? __ldg(bias + c1) : 0.f;
    const int   bb  = bag0 + warp * 4;

    out[(bb + 0) * NUM_CLASSES + lane] = acc00 + b0v;
    out[(bb + 1) * NUM_CLASSES + lane] = acc10 + b0v;
    out[(bb + 2) * NUM_CLASSES + lane] = acc20 + b0v;
    out[(bb + 3) * NUM_CLASSES + lane] = acc30 + b0v;
    if (c1 < NUM_CLASSES) {
        out[(bb + 0) * NUM_CLASSES + c1] = acc01 + b1v;
        out[(bb + 1) * NUM_CLASSES + c1] = acc11 + b1v;
        out[(bb + 2) * NUM_CLASSES + c1] = acc21 + b1v;
        out[(bb + 3) * NUM_CLASSES + c1] = acc31 + b1v;
    }
}

// ---------------------------------------------------------------------------
extern "C" void kernel_launch(void* const* d_in, const int* in_sizes, int n_in,
                              void* d_out, int out_size)
{
    const float* x    = (const float*)d_in[0];   // [262144, 256]
    const float* e0   = (const float*)d_in[1];   // [14, 256]
    const float* e1   = (const float*)d_in[2];   // [53, 256]
    const float* disc = (const float*)d_in[3];   // [53, 512]
    const float* bias = (const float*)d_in[4];   // [53]
    const int*   rl   = (const int*)d_in[5];     // [53, 2]
    const int*   li   = (const int*)d_in[6];     // [262144]
    const int*   sc   = (const int*)d_in[7];     // [4097]
    float* out = (float*)d_out;                  // [4096, 53]

    logits_kernel<<<N_SENT / 32, 256>>>((const float4*)x, e0, e1, rl, li);
    weights_kernel<<<N_BAGS / 8, 256>>>(sc);
    bag_kernel<<<N_BAGS, 256>>>((const float4*)x, sc);
    gemm_kernel<<<N_BAGS / K3_BAGS, 256>>>(disc, bias, out);
}

// round 12
// speedup vs baseline: 1.0857x; 1.0096x over previous
#include <cuda_runtime.h>
#include <math.h>

#define N_SENT      262144
#define N_BAGS      4096
#define HIDDEN      256
#define NUM_CLASSES 53
#define CH          512    // weight chunk staged in smem per iteration

// Static scratch (no allocs allowed).
__device__ float2 g_logits[N_SENT];        // logits, then unnormalized e
__device__ float2 g_stats[N_BAGS];         // (1/sum0, 1/sum1), 0 if empty
__device__ float  g_repre[N_BAGS * 512];   // [B, 2*HIDDEN]

// ---------------------------------------------------------------------------
// K1: per-sentence logits. 4 sentences per warp; contiguous-half addressing.
// ---------------------------------------------------------------------------
__global__ __launch_bounds__(256) void logits_kernel(
    const float4* __restrict__ x4,     // [N_SENT, 64]
    const float*  __restrict__ e0,     // [14, 256]
    const float*  __restrict__ e1,     // [53, 256]
    const int*    __restrict__ rl,     // [53, 2]
    const int*    __restrict__ li)     // [N_SENT]
{
    const int warp = threadIdx.x >> 5;
    const int lane = threadIdx.x & 31;
    const int base = (blockIdx.x * 8 + warp) * 4;   // grid 8192 covers N_SENT

    const int4 liv = __ldg(reinterpret_cast<const int4*>(li + base));
    int cs[4] = {liv.x, liv.y, liv.z, liv.w};

    const float4* xp = x4 + (size_t)base * 64;
    float4 XA[4], XB[4];
    #pragma unroll
    for (int s = 0; s < 4; s++) {
        XA[s] = __ldg(xp + s * 64 + lane);
        XB[s] = __ldg(xp + s * 64 + 32 + lane);
    }

    float g0[4], g1[4];
    #pragma unroll
    for (int s = 0; s < 4; s++) {
        int l0 = __ldg(rl + 2 * cs[s]);
        int l1 = __ldg(rl + 2 * cs[s] + 1);
        const float4* p0 = reinterpret_cast<const float4*>(e0 + l0 * HIDDEN);
        const float4* p1 = reinterpret_cast<const float4*>(e1 + l1 * HIDDEN);
        float4 ea = __ldg(p0 + lane), eb = __ldg(p0 + 32 + lane);
        float4 fa = __ldg(p1 + lane), fb = __ldg(p1 + 32 + lane);
        float4 xa = XA[s], xb = XB[s];
        g0[s] = xa.x*ea.x + xa.y*ea.y + xa.z*ea.z + xa.w*ea.w
              + xb.x*eb.x + xb.y*eb.y + xb.z*eb.z + xb.w*eb.w;
        g1[s] = xa.x*fa.x + xa.y*fa.y + xa.z*fa.z + xa.w*fa.w
              + xb.x*fb.x + xb.y*fb.y + xb.z*fb.z + xb.w*fb.w;
    }

    #pragma unroll
    for (int s = 0; s < 4; s++) {
        #pragma unroll
        for (int o = 16; o; o >>= 1) {
            g0[s] += __shfl_xor_sync(0xffffffffu, g0[s], o);
            g1[s] += __shfl_xor_sync(0xffffffffu, g1[s], o);
        }
    }
    if (lane == 0) {
        #pragma unroll
        for (int s = 0; s < 4; s++)
            g_logits[base + s] = make_float2(g0[s], g1[s]);
    }
}

// ---------------------------------------------------------------------------
// K2a: warp-per-bag softmax. Rewrites g_logits with unnormalized e,
//      stores 1/sum (0 for empty bag) in g_stats.
// ---------------------------------------------------------------------------
__global__ __launch_bounds__(256) void weights_kernel(
    const int* __restrict__ scope)     // [N_BAGS + 1]
{
    const int warp = threadIdx.x >> 5;
    const int lane = threadIdx.x & 31;
    const int bag  = blockIdx.x * 8 + warp;   // grid 512 covers N_BAGS

    const int s0 = __ldg(scope + bag);
    const int s1 = __ldg(scope + bag + 1);

    float m0 = -INFINITY, m1 = -INFINITY;
    for (int i = s0 + lane; i < s1; i += 32) {
        float2 v = g_logits[i];
        m0 = fmaxf(m0, v.x); m1 = fmaxf(m1, v.y);
    }
    #pragma unroll
    for (int o = 16; o; o >>= 1) {
        m0 = fmaxf(m0, __shfl_xor_sync(0xffffffffu, m0, o));
        m1 = fmaxf(m1, __shfl_xor_sync(0xffffffffu, m1, o));
    }

    float s0v = 0.f, s1v = 0.f;
    for (int i = s0 + lane; i < s1; i += 32) {
        float2 v = g_logits[i];
        float e0v = __expf(v.x - m0);
        float e1v = __expf(v.y - m1);
        s0v += e0v; s1v += e1v;
        g_logits[i] = make_float2(e0v, e1v);
    }
    #pragma unroll
    for (int o = 16; o; o >>= 1) {
        s0v += __shfl_xor_sync(0xffffffffu, s0v, o);
        s1v += __shfl_xor_sync(0xffffffffu, s1v, o);
    }
    if (lane == 0)
        g_stats[bag] = make_float2(s0v > 0.f ? 1.0f / s0v : 0.f,
                                   s1v > 0.f ? 1.0f / s1v : 0.f);
}

// ---------------------------------------------------------------------------
// K2: one block per bag. Warp = sentence subgroup (stride 8), lane covers
//     float4 columns lane and lane+32. Unroll-2 sentences -> 4 loads in
//     flight with only 2 sentences per warp. Single-barrier 8-way combine.
// ---------------------------------------------------------------------------
__global__ __launch_bounds__(256) void bag_kernel(
    const float4* __restrict__ x4,     // [N_SENT, 64]
    const int*    __restrict__ scope)  // [N_BAGS + 1]
{
    __shared__ float2 s_w[CH];         // 4 KB
    __shared__ float  s_c[8 * 512];    // 16 KB combine scratch

    const int b    = blockIdx.x;
    const int tid  = threadIdx.x;
    const int lane = tid & 31;
    const int w    = tid >> 5;         // subgroup 0..7

    const int s0 = __ldg(scope + b);
    const int s1 = __ldg(scope + b + 1);
    const int n  = s1 - s0;
    const float2 iv = g_stats[b];

    // accumulators: [level][column-half]
    float4 A0a = make_float4(0.f,0.f,0.f,0.f), A0b = make_float4(0.f,0.f,0.f,0.f);
    float4 A1a = make_float4(0.f,0.f,0.f,0.f), A1b = make_float4(0.f,0.f,0.f,0.f);

    for (int cstart = 0; cstart < n; cstart += CH) {
        int cn = min(CH, n - cstart);
        __syncthreads();
        for (int i = tid; i < cn; i += 256)
            s_w[i] = g_logits[s0 + cstart + i];
        __syncthreads();

        const float4* xb = x4 + (size_t)(s0 + cstart) * 64;
        int j = w;
        for (; j + 8 < cn; j += 16) {
            const float4* r0 = xb + (size_t)j * 64;
            const float4* r1 = xb + (size_t)(j + 8) * 64;
            float4 xa0 = __ldg(r0 + lane);
            float4 xb0 = __ldg(r0 + 32 + lane);
            float4 xa1 = __ldg(r1 + lane);
            float4 xb1 = __ldg(r1 + 32 + lane);
            float2 w0 = s_w[j], w1 = s_w[j + 8];
            A0a.x += w0.x*xa0.x; A0a.y += w0.x*xa0.y; A0a.z += w0.x*xa0.z; A0a.w += w0.x*xa0.w;
            A1a.x += w0.y*xa0.x; A1a.y += w0.y*xa0.y; A1a.z += w0.y*xa0.z; A1a.w += w0.y*xa0.w;
            A0b.x += w0.x*xb0.x; A0b.y += w0.x*xb0.y; A0b.z += w0.x*xb0.z; A0b.w += w0.x*xb0.w;
            A1b.x += w0.y*xb0.x; A1b.y += w0.y*xb0.y; A1b.z += w0.y*xb0.z; A1b.w += w0.y*xb0.w;
            A0a.x += w1.x*xa1.x; A0a.y += w1.x*xa1.y; A0a.z += w1.x*xa1.z; A0a.w += w1.x*xa1.w;
            A1a.x += w1.y*xa1.x; A1a.y += w1.y*xa1.y; A1a.z += w1.y*xa1.z; A1a.w += w1.y*xa1.w;
            A0b.x += w1.x*xb1.x; A0b.y += w1.x*xb1.y; A0b.z += w1.x*xb1.z; A0b.w += w1.x*xb1.w;
            A1b.x += w1.y*xb1.x; A1b.y += w1.y*xb1.y; A1b.z += w1.y*xb1.z; A1b.w += w1.y*xb1.w;
        }
        if (j < cn) {
            const float4* r0 = xb + (size_t)j * 64;
            float4 xa0 = __ldg(r0 + lane);
            float4 xb0 = __ldg(r0 + 32 + lane);
            float2 w0 = s_w[j];
            A0a.x += w0.x*xa0.x; A0a.y += w0.x*xa0.y; A0a.z += w0.x*xa0.z; A0a.w += w0.x*xa0.w;
            A1a.x += w0.y*xa0.x; A1a.y += w0.y*xa0.y; A1a.z += w0.y*xa0.z; A1a.w += w0.y*xa0.w;
            A0b.x += w0.x*xb0.x; A0b.y += w0.x*xb0.y; A0b.z += w0.x*xb0.z; A0b.w += w0.x*xb0.w;
            A1b.x += w0.y*xb0.x; A1b.y += w0.y*xb0.y; A1b.z += w0.y*xb0.z; A1b.w += w0.y*xb0.w;
        }
    }

    // single-barrier combine: s_c[w][level*256 + dim]
    __syncthreads();   // all readers of s_w done; also orders s_c reuse
    *reinterpret_cast<float4*>(&s_c[w * 512 + 4 * lane])       = A0a;   // dims 0..127, lvl0
    *reinterpret_cast<float4*>(&s_c[w * 512 + 128 + 4 * lane]) = A0b;   // dims 128..255
    *reinterpret_cast<float4*>(&s_c[w * 512 + 256 + 4 * lane]) = A1a;   // lvl1
    *reinterpret_cast<float4*>(&s_c[w * 512 + 384 + 4 * lane]) = A1b;
    __syncthreads();

    float r0 = 0.f, r1 = 0.f;
    #pragma unroll
    for (int g = 0; g < 8; g++) {
        r0 += s_c[g * 512 + tid];
        r1 += s_c[g * 512 + 256 + tid];
    }
    g_repre[(size_t)b * 512 + tid]       = r0 * iv.x;
    g_repre[(size_t)b * 512 + 256 + tid] = r1 * iv.y;
}

// ---------------------------------------------------------------------------
// K3: out[4096,53] = repre[4096,512] @ disc[53,512]^T + bias.
//     grid 256 x 16 bags; per-thread tile 2 bags x 2 classes.
// ---------------------------------------------------------------------------
#define K3_BAGS 16
#define KC      64
__global__ __launch_bounds__(256) void gemm_kernel(
    const float* __restrict__ disc,    // [53, 512]
    const float* __restrict__ bias,    // [53]
    float*       __restrict__ out)     // [N_BAGS, 53]
{
    __shared__ float s_rep[K3_BAGS * 68];
    __shared__ float s_disc[NUM_CLASSES * 68];

    const int tid  = threadIdx.x;
    const int lane = tid & 31;
    const int warp = tid >> 5;
    const int bag0 = blockIdx.x * K3_BAGS;

    float a00 = 0.f, a01 = 0.f, a10 = 0.f, a11 = 0.f;

    const float4* rep4 = reinterpret_cast<const float4*>(g_repre);
    const int c1  = 32 + lane;
    const int c1c = (c1 < NUM_CLASSES) ? c1 : lane;

    for (int k0 = 0; k0 < 512; k0 += KC) {
        __syncthreads();
        // stage rep tile: 16 bags x 16 float4 = 256
        {
            int bg = tid >> 4, q = tid & 15;
            float4 v = rep4[(size_t)(bag0 + bg) * 128 + (k0 >> 2) + q];
            *reinterpret_cast<float4*>(&s_rep[bg * 68 + q * 4]) = v;
        }
        // stage disc tile: 53 x 16 float4 = 848
        #pragma unroll
        for (int p = 0; p < 4; p++) {
            int f = tid + p * 256;
            if (f < NUM_CLASSES * 16) {
                int c = f >> 4, q = f & 15;
                float4 v = __ldg(reinterpret_cast<const float4*>(disc + c * 512 + k0) + q);
                *reinterpret_cast<float4*>(&s_disc[c * 68 + q * 4]) = v;
            }
        }
        __syncthreads();

        #pragma unroll
        for (int q = 0; q < 16; q++) {
            float4 bv0 = *reinterpret_cast<const float4*>(&s_disc[lane * 68 + q * 4]);
            float4 bv1 = *reinterpret_cast<const float4*>(&s_disc[c1c * 68 + q * 4]);
            float4 av0 = *reinterpret_cast<const float4*>(&s_rep[(warp * 2 + 0) * 68 + q * 4]);
            float4 av1 = *reinterpret_cast<const float4*>(&s_rep[(warp * 2 + 1) * 68 + q * 4]);
            a00 += av0.x*bv0.x + av0.y*bv0.y + av0.z*bv0.z + av0.w*bv0.w;
            a01 += av0.x*bv1.x + av0.y*bv1.y + av0.z*bv1.z + av0.w*bv1.w;
            a10 += av1.x*bv0.x + av1.y*bv0.y + av1.z*bv0.z + av1.w*bv0.w;
            a11 += av1.x*bv1.x + av1.y*bv1.y + av1.z*bv1.z + av1.w*bv1.w;
        }
    }

    const float b0v = __ldg(bias + lane);
    const float b1v = (c1 < NUM_CLASSES) ? __ldg(bias + c1) : 0.f;
    const int   bb  = bag0 + warp * 2;

    out[(bb + 0) * NUM_CLASSES + lane] = a00 + b0v;
    out[(bb + 1) * NUM_CLASSES + lane] = a10 + b0v;
    if (c1 < NUM_CLASSES) {
        out[(bb + 0) * NUM_CLASSES + c1] = a01 + b1v;
        out[(bb + 1) * NUM_CLASSES + c1] = a11 + b1v;
    }
}

// ---------------------------------------------------------------------------
extern "C" void kernel_launch(void* const* d_in, const int* in_sizes, int n_in,
                              void* d_out, int out_size)
{
    const float* x    = (const float*)d_in[0];   // [262144, 256]
    const float* e0   = (const float*)d_in[1];   // [14, 256]
    const float* e1   = (const float*)d_in[2];   // [53, 256]
    const float* disc = (const float*)d_in[3];   // [53, 512]
    const float* bias = (const float*)d_in[4];   // [53]
    const int*   rl   = (const int*)d_in[5];     // [53, 2]
    const int*   li   = (const int*)d_in[6];     // [262144]
    const int*   sc   = (const int*)d_in[7];     // [4097]
    float* out = (float*)d_out;                  // [4096, 53]

    logits_kernel<<<N_SENT / 32, 256>>>((const float4*)x, e0, e1, rl, li);
    weights_kernel<<<N_BAGS / 8, 256>>>(sc);
    bag_kernel<<<N_BAGS, 256>>>((const float4*)x, sc);
    gemm_kernel<<<N_BAGS / K3_BAGS, 256>>>(disc, bias, out);
}